// round 16
// baseline (speedup 1.0000x reference)
#include <cuda_runtime.h>
#include <cuda_fp16.h>
#include <cstdint>

typedef __half f16;

#define CTXL 8192
#define QL   128
#define KVL  8320
#define HIDN 4096
#define NH   32
#define NKV  8
#define HD   128
#define KVROWS (4 * KVL)          // 33280

// ---------------- scratch ----------------
__device__ float g_q_raw[4 * QL * HIDN];
__device__ float g_k_raw[(size_t)KVROWS * NKV * HD];

__device__ f16 g_Wqh[(size_t)NH * HD * HIDN];
__device__ f16 g_Wkvh[(size_t)2 * NKV * HD * HIDN];
__device__ f16 g_Woh[(size_t)HIDN * NH * HD];
__device__ f16 g_hh[4 * QL * HIDN], g_hl[4 * QL * HIDN];
__device__ f16 g_kvh[(size_t)KVROWS * HIDN], g_kvl[(size_t)KVROWS * HIDN];
__device__ f16 g_Qh[4 * NH * QL * HD], g_Ql[4 * NH * QL * HD];
__device__ f16 g_Kh[(size_t)4 * NKV * KVL * HD];
__device__ f16 g_Vh[(size_t)KVROWS * NKV * HD];
__device__ f16 g_ah[4 * QL * HIDN], g_al[4 * QL * HIDN];

// ================= helpers =================
__device__ __forceinline__ uint32_t smem_u32(const void* p) {
    uint32_t a;
    asm("{ .reg .u64 t; cvta.to.shared.u64 t, %1; cvt.u32.u64 %0, t; }" : "=r"(a) : "l"(p));
    return a;
}
__device__ __forceinline__ void ldsm_x4(uint32_t addr, uint32_t* r) {
    asm volatile("ldmatrix.sync.aligned.m8n8.x4.shared.b16 {%0,%1,%2,%3}, [%4];"
                 : "=r"(r[0]), "=r"(r[1]), "=r"(r[2]), "=r"(r[3]) : "r"(addr));
}
__device__ __forceinline__ void ldsm_x4_t(uint32_t addr, uint32_t* r) {
    asm volatile("ldmatrix.sync.aligned.m8n8.x4.trans.shared.b16 {%0,%1,%2,%3}, [%4];"
                 : "=r"(r[0]), "=r"(r[1]), "=r"(r[2]), "=r"(r[3]) : "r"(addr));
}
__device__ __forceinline__ void mma16816(float* c, const uint32_t* a, const uint32_t* b) {
    asm volatile(
        "mma.sync.aligned.m16n8k16.row.col.f32.f16.f16.f32 "
        "{%0,%1,%2,%3}, {%4,%5,%6,%7}, {%8,%9}, {%0,%1,%2,%3};"
        : "+f"(c[0]), "+f"(c[1]), "+f"(c[2]), "+f"(c[3])
        : "r"(a[0]), "r"(a[1]), "r"(a[2]), "r"(a[3]), "r"(b[0]), "r"(b[1]));
}
__device__ __forceinline__ void cpa16(uint32_t dst, const void* src) {
    asm volatile("cp.async.cg.shared.global [%0], [%1], 16;" :: "r"(dst), "l"(src));
}
__device__ __forceinline__ void cpa_commit() { asm volatile("cp.async.commit_group;"); }
template <int N>
__device__ __forceinline__ void cpa_wait() { asm volatile("cp.async.wait_group %0;" :: "n"(N)); }

__device__ __forceinline__ void split1h(float x, unsigned& h, unsigned& l) {
    f16 hb = __float2half_rn(x);
    float r = x - __half2float(hb);
    f16 lb = __float2half_rn(r);
    h = (unsigned)__half_as_ushort(hb);
    l = (unsigned)__half_as_ushort(lb);
}

// ---------------- conversion kernels ----------------
__global__ void split_pair(const float* __restrict__ in, f16* __restrict__ hi,
                           f16* __restrict__ lo, size_t n8)
{
    const size_t i = (size_t)blockIdx.x * 256 + threadIdx.x;
    if (i >= n8) return;
    const float* s = in + i * 8;
    unsigned h[8], l[8];
#pragma unroll
    for (int k = 0; k < 8; k++) split1h(s[k], h[k], l[k]);
    *(uint4*)(hi + i * 8) = make_uint4(h[0] | (h[1] << 16), h[2] | (h[3] << 16),
                                       h[4] | (h[5] << 16), h[6] | (h[7] << 16));
    *(uint4*)(lo + i * 8) = make_uint4(l[0] | (l[1] << 16), l[2] | (l[3] << 16),
                                       l[4] | (l[5] << 16), l[6] | (l[7] << 16));
}

__global__ void conv_hi(const float* __restrict__ in, f16* __restrict__ hi, size_t n8)
{
    const size_t i = (size_t)blockIdx.x * 256 + threadIdx.x;
    if (i >= n8) return;
    const float* s = in + i * 8;
    unsigned h[8];
#pragma unroll
    for (int k = 0; k < 8; k++)
        h[k] = (unsigned)__half_as_ushort(__float2half_rn(s[k]));
    *(uint4*)(hi + i * 8) = make_uint4(h[0] | (h[1] << 16), h[2] | (h[3] << 16),
                                       h[4] | (h[5] << 16), h[6] | (h[7] << 16));
}

__global__ void split_kv(const float* __restrict__ hidden, const float* __restrict__ target,
                         f16* __restrict__ hi, f16* __restrict__ lo)
{
    const int row = blockIdx.y;
    const int b = row / KVL;
    const int t = row - b * KVL;
    const float* src = (t < CTXL) ? target + ((size_t)b * CTXL + t) * HIDN
                                  : hidden + ((size_t)b * QL + (t - CTXL)) * HIDN;
    const int col = (blockIdx.x * 256 + threadIdx.x) * 8;
    const float* s = src + col;
    unsigned h[8], l[8];
#pragma unroll
    for (int k = 0; k < 8; k++) split1h(s[k], h[k], l[k]);
    *(uint4*)(hi + (size_t)row * HIDN + col) =
        make_uint4(h[0] | (h[1] << 16), h[2] | (h[3] << 16),
                   h[4] | (h[5] << 16), h[6] | (h[7] << 16));
    *(uint4*)(lo + (size_t)row * HIDN + col) =
        make_uint4(l[0] | (l[1] << 16), l[2] | (l[3] << 16),
                   l[4] | (l[5] << 16), l[6] | (l[7] << 16));
}

// ============ GEMM: 128x128, 256 thr, KC=32; NSTG/MINCTA templated ============
// OUTMODE 0: fp32 C.  OUTMODE 2: fused KV — K tiles (n0<1024): 2-term A, fp32 k_raw;
// V tiles (n0>=1024): 1-term A, fp16 V plane.
// KV GEMM uses NSTG=2 / MINCTA=3 (24 warps/SM); Q/O use NSTG=3 / MINCTA=2.
#define ROWB 80
#define TILEB (128 * ROWB)          // 10240
#define STAGEB (3 * TILEB)          // 30720 (Ah, Al, Bh)

template <int OUTMODE, int NSTG, int MINCTA>
__global__ void __launch_bounds__(256, MINCTA)
gemm3(const f16* __restrict__ Ah, const f16* __restrict__ Al,
      const f16* __restrict__ Bh,
      float* __restrict__ C, f16* __restrict__ Ch,
      int M, int N, int K)
{
    extern __shared__ char sm[];
    const uint32_t smb = smem_u32(sm);
    const int tid = threadIdx.x;
    const int l = tid & 31;
    const int w = tid >> 5;

    const int m0 = blockIdx.y * 128;
    const int n0 = blockIdx.x * 128;
    const bool useLo = (OUTMODE != 2) || (n0 < 1024);

    const int lrow = tid >> 1;
    const int lseg = tid & 1;
    const f16* ah = Ah + (size_t)(m0 + lrow) * K + lseg * 16;
    const f16* al = Al + (size_t)(m0 + lrow) * K + lseg * 16;
    const f16* bh = Bh + (size_t)(n0 + lrow) * K + lseg * 16;
    const uint32_t soff = (uint32_t)lrow * ROWB + (uint32_t)lseg * 32;

    const int wm = (w & 3) * 32;
    const int wn = (w >> 2) * 64;
    const uint32_t a_off = (uint32_t)(wm + (l & 15)) * ROWB + (uint32_t)(l >> 4) * 16;
    const uint32_t b_off = (uint32_t)(wn + (l & 7) + ((l >> 4) & 1) * 8) * ROWB
                         + (uint32_t)((l >> 3) & 1) * 16;

    float acc[2][8][4];
#pragma unroll
    for (int i = 0; i < 2; i++)
#pragma unroll
        for (int j = 0; j < 8; j++)
#pragma unroll
            for (int k = 0; k < 4; k++) acc[i][j][k] = 0.f;

    const int nk = K / 32;

    auto issue = [&](int cc, int st) {
        const uint32_t s0 = smb + (uint32_t)st * STAGEB + soff;
        const int ko = cc * 32;
        cpa16(s0,             ah + ko);  cpa16(s0 + 16,             ah + ko + 8);
        if (useLo) {
            cpa16(s0 + TILEB,     al + ko);  cpa16(s0 + TILEB + 16,     al + ko + 8);
        }
        cpa16(s0 + 2 * TILEB, bh + ko);  cpa16(s0 + 2 * TILEB + 16, bh + ko + 8);
    };

    if (NSTG == 3) {
        issue(0, 0); cpa_commit();
        issue(1, 1); cpa_commit();
    } else {
        issue(0, 0); cpa_commit();
    }

    for (int c = 0; c < nk; ++c) {
        if (NSTG == 3) {
            cpa_wait<1>();
            __syncthreads();
            if (c + 2 < nk) issue(c + 2, (c + 2) % 3);
            cpa_commit();
        } else {
            if (c + 1 < nk) {
                issue(c + 1, (c + 1) & 1);
                cpa_commit();
                cpa_wait<1>();
            } else {
                cpa_wait<0>();
            }
            __syncthreads();
        }

        const uint32_t base = smb + (uint32_t)(NSTG == 3 ? (c % 3) : (c & 1)) * STAGEB;
#pragma unroll
        for (int ks = 0; ks < 2; ++ks) {
            uint32_t afh[2][4], afl[2][4];
            const uint32_t ka = base + a_off + ks * 32;
            ldsm_x4(ka, afh[0]);
            ldsm_x4(ka + 16 * ROWB, afh[1]);
            if (useLo) {
                ldsm_x4(ka + TILEB, afl[0]);
                ldsm_x4(ka + TILEB + 16 * ROWB, afl[1]);
            }

            const uint32_t kb = base + 2 * TILEB + b_off + ks * 32;
#pragma unroll
            for (int ng = 0; ng < 4; ++ng) {
                uint32_t bfh[4];
                ldsm_x4(kb + ng * 16 * ROWB, bfh);
#pragma unroll
                for (int mf = 0; mf < 2; ++mf) {
                    mma16816(acc[mf][ng * 2 + 0], afh[mf], bfh + 0);
                    mma16816(acc[mf][ng * 2 + 1], afh[mf], bfh + 2);
                }
                if (useLo) {
#pragma unroll
                    for (int mf = 0; mf < 2; ++mf) {
                        mma16816(acc[mf][ng * 2 + 0], afl[mf], bfh + 0);
                        mma16816(acc[mf][ng * 2 + 1], afl[mf], bfh + 2);
                    }
                }
            }
        }
        if (NSTG == 2) __syncthreads();   // readers done before next issue overwrites
    }

#pragma unroll
    for (int mf = 0; mf < 2; ++mf) {
        const int r0 = m0 + wm + mf * 16 + (l >> 2);
#pragma unroll
        for (int nf = 0; nf < 8; ++nf) {
            const int col = n0 + wn + nf * 8 + (l & 3) * 2;
            if (OUTMODE == 0) {
                float* p = C + (size_t)r0 * N + col;
                *(float2*)p                   = make_float2(acc[mf][nf][0], acc[mf][nf][1]);
                *(float2*)(p + 8 * (size_t)N) = make_float2(acc[mf][nf][2], acc[mf][nf][3]);
            } else {
                if (n0 < 1024) {
                    float* p = C + (size_t)r0 * 1024 + col;
                    *(float2*)p              = make_float2(acc[mf][nf][0], acc[mf][nf][1]);
                    *(float2*)(p + 8 * 1024) = make_float2(acc[mf][nf][2], acc[mf][nf][3]);
                } else {
                    const int vcol = col - 1024;
                    unsigned h0 = (unsigned)__half_as_ushort(__float2half_rn(acc[mf][nf][0]));
                    unsigned h1 = (unsigned)__half_as_ushort(__float2half_rn(acc[mf][nf][1]));
                    unsigned h2 = (unsigned)__half_as_ushort(__float2half_rn(acc[mf][nf][2]));
                    unsigned h3 = (unsigned)__half_as_ushort(__float2half_rn(acc[mf][nf][3]));
                    *(uint32_t*)(Ch + (size_t)r0 * 1024 + vcol)       = h0 | (h1 << 16);
                    *(uint32_t*)(Ch + (size_t)(r0 + 8) * 1024 + vcol) = h2 | (h3 << 16);
                }
            }
        }
    }
}

// ---------------- norm+rope v3 (R12): one warp per head-row ----------------
template <int TWOPLANE>
__global__ void __launch_bounds__(256)
norm_rope3(const float* __restrict__ raw, f16* __restrict__ oh, f16* __restrict__ ol,
           const float* __restrict__ w,
           const float* __restrict__ cosb, const float* __restrict__ sinb,
           int heads, int seq, int rawld, int pos_off, float outscale)
{
    const int gid = blockIdx.x * 8 + (threadIdx.x >> 5);
    const int l = threadIdx.x & 31;
    const int t = gid % seq;
    const int h = (gid / seq) % heads;
    const int b = gid / (seq * heads);
    const int d = l * 4;

    const float4 x  = *(const float4*)(raw + ((size_t)(b * seq + t)) * rawld + h * HD + d);
    const float4 wv = *(const float4*)(w + d);
    float ss = x.x * x.x + x.y * x.y + x.z * x.z + x.w * x.w;
#pragma unroll
    for (int off = 16; off > 0; off >>= 1)
        ss += __shfl_xor_sync(0xffffffffu, ss, off);
    const float r = rsqrtf(ss * (1.0f / 128.0f) + 1e-6f);

    const float xn0 = x.x * r * wv.x;
    const float xn1 = x.y * r * wv.y;
    const float xn2 = x.z * r * wv.z;
    const float xn3 = x.w * r * wv.w;

    const float p0 = __shfl_xor_sync(0xffffffffu, xn0, 16);
    const float p1 = __shfl_xor_sync(0xffffffffu, xn1, 16);
    const float p2 = __shfl_xor_sync(0xffffffffu, xn2, 16);
    const float p3 = __shfl_xor_sync(0xffffffffu, xn3, 16);
    const float sgn = (l < 16) ? -1.f : 1.f;

    const size_t pidx = ((size_t)b * KVL + (size_t)(pos_off + t)) * HD + d;
    const float4 cv = *(const float4*)(cosb + pidx);
    const float4 sv = *(const float4*)(sinb + pidx);

    const float y0 = (xn0 * cv.x + sgn * p0 * sv.x) * outscale;
    const float y1 = (xn1 * cv.y + sgn * p1 * sv.y) * outscale;
    const float y2 = (xn2 * cv.z + sgn * p2 * sv.z) * outscale;
    const float y3 = (xn3 * cv.w + sgn * p3 * sv.w) * outscale;

    const size_t o = (((size_t)(b * heads + h)) * seq + t) * HD + d;
    if (TWOPLANE) {
        unsigned h0, l0, h1, l1, h2, l2, h3, l3;
        split1h(y0, h0, l0); split1h(y1, h1, l1);
        split1h(y2, h2, l2); split1h(y3, h3, l3);
        *(uint2*)(oh + o) = make_uint2(h0 | (h1 << 16), h2 | (h3 << 16));
        *(uint2*)(ol + o) = make_uint2(l0 | (l1 << 16), l2 | (l3 << 16));
    } else {
        const __half2 a = __floats2half2_rn(y0, y1);
        const __half2 bpk = __floats2half2_rn(y2, y3);
        *(uint2*)(oh + o) = make_uint2(*(const uint32_t*)&a, *(const uint32_t*)&bpk);
    }
}

// ---------------- flash attention (R12 exact) ----------------
#define QROWB 272
#define QTILE (128 * QROWB)
#define ATT_K0 (2 * QTILE)
#define ATT_V0 (4 * QTILE)
#define ATT_SMEM (6 * QTILE)
#define NCHUNK (KVL / 128)

__global__ void __launch_bounds__(256, 1)
attn4(const f16* __restrict__ Qh, const f16* __restrict__ Ql,
      const f16* __restrict__ Kh, const f16* __restrict__ Vh,
      f16* __restrict__ Oh, f16* __restrict__ Ol)
{
    extern __shared__ char sm[];
    const uint32_t smb = smem_u32(sm);

    const int b   = blockIdx.x >> 5;
    const int h   = blockIdx.x & 31;
    const int kvh = h >> 2;
    const int tid = threadIdx.x;
    const int l = tid & 31;
    const int w = tid >> 5;

    const int row = tid >> 1;
    const int half = tid & 1;
    const uint32_t ld_off = (uint32_t)row * QROWB + (uint32_t)half * 128;

    {
        const f16* qh = Qh + ((size_t)(b * NH + h) * QL + row) * HD + half * 64;
        const f16* ql = Ql + ((size_t)(b * NH + h) * QL + row) * HD + half * 64;
#pragma unroll
        for (int i = 0; i < 8; i++) {
            cpa16(smb + ld_off + i * 16, qh + i * 8);
            cpa16(smb + QTILE + ld_off + i * 16, ql + i * 8);
        }
        cpa_commit();
    }

    const f16* kg = Kh + (size_t)(b * NKV + kvh) * KVL * HD;
    const f16* vg = Vh + (size_t)b * KVL * (NKV * HD) + kvh * HD;

    auto issue_chunk = [&](int cc) {
        const int st = cc & 1;
        const int t0 = cc * 128;
        const f16* s1 = kg + (size_t)(t0 + row) * HD + half * 64;
        const f16* s2 = vg + (size_t)(t0 + row) * (NKV * HD) + half * 64;
        const uint32_t kb = smb + ATT_K0 + (uint32_t)st * QTILE + ld_off;
        const uint32_t vb = smb + ATT_V0 + (uint32_t)st * QTILE + ld_off;
#pragma unroll
        for (int i = 0; i < 8; i++) {
            cpa16(kb + i * 16, s1 + i * 8);
            cpa16(vb + i * 16, s2 + i * 8);
        }
    };

    issue_chunk(0); cpa_commit();

    const int wq = w * 16;
    const uint32_t qa_off = (uint32_t)(wq + (l & 15)) * QROWB + (uint32_t)(l >> 4) * 16;
    const uint32_t kb_off = (uint32_t)((l & 7) + ((l >> 4) & 1) * 8) * QROWB
                          + (uint32_t)((l >> 3) & 1) * 16;
    const uint32_t vb_off = (uint32_t)(l & 15) * QROWB + (uint32_t)((l >> 4) & 1) * 16;

    float O[16][4];
    float mr[2], lr[2];
#pragma unroll
    for (int i = 0; i < 16; i++)
#pragma unroll
        for (int j = 0; j < 4; j++) O[i][j] = 0.f;
    mr[0] = mr[1] = -1e30f;
    lr[0] = lr[1] = 0.f;

    for (int c = 0; c < NCHUNK; ++c) {
        if (c + 1 < NCHUNK) issue_chunk(c + 1);
        cpa_commit();
        cpa_wait<1>();
        __syncthreads();

        const uint32_t sK = smb + ATT_K0 + (uint32_t)(c & 1) * QTILE;
        const uint32_t sV = smb + ATT_V0 + (uint32_t)(c & 1) * QTILE;

        float S[16][4];
#pragma unroll
        for (int i = 0; i < 16; i++)
#pragma unroll
            for (int j = 0; j < 4; j++) S[i][j] = 0.f;

#pragma unroll
        for (int ds = 0; ds < 8; ++ds) {
            uint32_t aqh[4], aql[4];
            ldsm_x4(smb + qa_off + ds * 32, aqh);
            ldsm_x4(smb + QTILE + qa_off + ds * 32, aql);
#pragma unroll
            for (int ng = 0; ng < 8; ++ng) {
                uint32_t bkh[4];
                ldsm_x4(sK + kb_off + ng * 16 * QROWB + ds * 32, bkh);
                mma16816(S[ng * 2 + 0], aqh, bkh + 0);
                mma16816(S[ng * 2 + 1], aqh, bkh + 2);
                mma16816(S[ng * 2 + 0], aql, bkh + 0);
                mma16816(S[ng * 2 + 1], aql, bkh + 2);
            }
        }

#pragma unroll
        for (int rr = 0; rr < 2; ++rr) {
            float mx = -1e30f;
#pragma unroll
            for (int t = 0; t < 16; t++)
                mx = fmaxf(mx, fmaxf(S[t][rr * 2], S[t][rr * 2 + 1]));
            mx = fmaxf(mx, __shfl_xor_sync(0xffffffffu, mx, 1));
            mx = fmaxf(mx, __shfl_xor_sync(0xffffffffu, mx, 2));
            const float mn = fmaxf(mr[rr], mx);
            const float corr = __expf(mr[rr] - mn);
            float rs = 0.f;
#pragma unroll
            for (int t = 0; t < 16; t++) {
                float p0 = __expf(S[t][rr * 2] - mn);
                float p1 = __expf(S[t][rr * 2 + 1] - mn);
                S[t][rr * 2] = p0;
                S[t][rr * 2 + 1] = p1;
                rs += p0 + p1;
            }
            rs += __shfl_xor_sync(0xffffffffu, rs, 1);
            rs += __shfl_xor_sync(0xffffffffu, rs, 2);
            lr[rr] = lr[rr] * corr + rs;
            mr[rr] = mn;
#pragma unroll
            for (int t = 0; t < 16; t++) {
                O[t][rr * 2] *= corr;
                O[t][rr * 2 + 1] *= corr;
            }
        }

#pragma unroll
        for (int s = 0; s < 8; ++s) {
            uint32_t ph[4];
#pragma unroll
            for (int q4 = 0; q4 < 4; ++q4) {
                const int t = 2 * s + (q4 >> 1);
                const __half2 pk = __floats2half2_rn(S[t][(q4 & 1) * 2],
                                                     S[t][(q4 & 1) * 2 + 1]);
                ph[q4] = *(const uint32_t*)&pk;
            }
#pragma unroll
            for (int ng = 0; ng < 8; ++ng) {
                uint32_t vbh[4];
                ldsm_x4_t(sV + vb_off + s * 16 * QROWB + ng * 32, vbh);
                mma16816(O[ng * 2 + 0], ph, vbh + 0);
                mma16816(O[ng * 2 + 1], ph, vbh + 2);
            }
        }
        __syncthreads();
    }

    const float inv0 = 1.0f / lr[0];
    const float inv1 = 1.0f / lr[1];
    const int q0 = wq + (l >> 2);
#pragma unroll
    for (int nf = 0; nf < 16; ++nf) {
        const int col = nf * 8 + (l & 3) * 2;
        unsigned h0, l0, h1, l1;
        split1h(O[nf][0] * inv0, h0, l0);
        split1h(O[nf][1] * inv0, h1, l1);
        size_t o = ((size_t)(b * QL + q0)) * HIDN + h * HD + col;
        *(uint32_t*)(Oh + o) = h0 | (h1 << 16);
        *(uint32_t*)(Ol + o) = l0 | (l1 << 16);
        split1h(O[nf][2] * inv1, h0, l0);
        split1h(O[nf][3] * inv1, h1, l1);
        o = ((size_t)(b * QL + q0 + 8)) * HIDN + h * HD + col;
        *(uint32_t*)(Oh + o) = h0 | (h1 << 16);
        *(uint32_t*)(Ol + o) = l0 | (l1 << 16);
    }
}

// ---------------- launcher: 3-stream capture-forked schedule ----------------
extern "C" void kernel_launch(void* const* d_in, const int* in_sizes, int n_in,
                              void* d_out, int out_size)
{
    const float* hidden = (const float*)d_in[0];
    const float* target = (const float*)d_in[1];
    const float* cosb   = (const float*)d_in[2];
    const float* sinb   = (const float*)d_in[3];
    const float* Wq     = (const float*)d_in[4];
    const float* Wk     = (const float*)d_in[5];
    const float* Wv     = (const float*)d_in[6];
    const float* Wo     = (const float*)d_in[7];
    const float* qw     = (const float*)d_in[8];
    const float* kw     = (const float*)d_in[9];
    float* out = (float*)d_out;

    float *q_raw, *k_raw;
    f16 *Wqh, *Wkvh, *Woh, *hh, *hl, *kvh_, *kvl_, *Qhp, *Qlp, *Khp, *Vhp, *ah, *al;
    cudaGetSymbolAddress((void**)&q_raw, g_q_raw);
    cudaGetSymbolAddress((void**)&k_raw, g_k_raw);
    cudaGetSymbolAddress((void**)&Wqh, g_Wqh);
    cudaGetSymbolAddress((void**)&Wkvh, g_Wkvh);
    cudaGetSymbolAddress((void**)&Woh, g_Woh);
    cudaGetSymbolAddress((void**)&hh, g_hh);    cudaGetSymbolAddress((void**)&hl, g_hl);
    cudaGetSymbolAddress((void**)&kvh_, g_kvh); cudaGetSymbolAddress((void**)&kvl_, g_kvl);
    cudaGetSymbolAddress((void**)&Qhp, g_Qh);   cudaGetSymbolAddress((void**)&Qlp, g_Ql);
    cudaGetSymbolAddress((void**)&Khp, g_Kh);
    cudaGetSymbolAddress((void**)&Vhp, g_Vh);
    cudaGetSymbolAddress((void**)&ah, g_ah);    cudaGetSymbolAddress((void**)&al, g_al);

    const int GEMM_SMEM2 = 2 * STAGEB;   // 61440: KV (2-stage, 3 CTAs/SM)
    const int GEMM_SMEM3 = 3 * STAGEB;   // 92160: Q/O (3-stage, 2 CTAs/SM)

    cudaFuncSetAttribute((const void*)gemm3<0, 3, 2>,
                         cudaFuncAttributeMaxDynamicSharedMemorySize, GEMM_SMEM3);
    cudaFuncSetAttribute((const void*)gemm3<2, 2, 3>,
                         cudaFuncAttributeMaxDynamicSharedMemorySize, GEMM_SMEM2);
    cudaFuncSetAttribute(attn4, cudaFuncAttributeMaxDynamicSharedMemorySize, ATT_SMEM);

    static cudaStream_t s2 = nullptr, s3 = nullptr;
    static cudaEvent_t evFork = nullptr, evJoin = nullptr, evW = nullptr;
    if (!s2) {
        cudaStreamCreateWithFlags(&s2, cudaStreamNonBlocking);
        cudaStreamCreateWithFlags(&s3, cudaStreamNonBlocking);
        cudaEventCreateWithFlags(&evFork, cudaEventDisableTiming);
        cudaEventCreateWithFlags(&evJoin, cudaEventDisableTiming);
        cudaEventCreateWithFlags(&evW, cudaEventDisableTiming);
    }

    const size_t WKV = (size_t)NKV * HD * HIDN;
    const float qscale = 0.08838834764831845f;

    // ---- fork ----
    cudaEventRecord(evFork, 0);
    cudaStreamWaitEvent(s2, evFork, 0);
    cudaStreamWaitEvent(s3, evFork, 0);

    // s3: KV weight converts
    conv_hi<<<(int)(WKV / 2048), 256, 0, s3>>>(Wk, Wkvh, WKV / 8);
    conv_hi<<<(int)(WKV / 2048), 256, 0, s3>>>(Wv, Wkvh + WKV, WKV / 8);
    cudaEventRecord(evW, s3);

    // s2: Q-chain + Wo convert
    conv_hi<<<(NH * HD * HIDN) / 2048, 256, 0, s2>>>(Wq, Wqh, (size_t)(NH * HD * HIDN) / 8);
    split_pair<<<(4 * QL * HIDN) / 2048, 256, 0, s2>>>(hidden, hh, hl,
                                                       (size_t)(4 * QL * HIDN) / 8);
    gemm3<0, 3, 2><<<dim3(HIDN / 128, (4 * QL) / 128), 256, GEMM_SMEM3, s2>>>(
        hh, hl, Wqh, q_raw, nullptr, 4 * QL, HIDN, HIDN);
    norm_rope3<1><<<(4 * NH * QL) / 8, 256, 0, s2>>>(q_raw, Qhp, Qlp, qw, cosb, sinb,
                                                     NH, QL, HIDN, CTXL, qscale);
    conv_hi<<<(HIDN * NH * HD) / 2048, 256, 0, s2>>>(Wo, Woh, (size_t)(HIDN * NH * HD) / 8);
    cudaEventRecord(evJoin, s2);

    // main: KV-chain (2-stage, 3 CTAs/SM)
    split_kv<<<dim3(HIDN / 2048, KVROWS), 256>>>(hidden, target, kvh_, kvl_);
    cudaStreamWaitEvent(0, evW, 0);
    gemm3<2, 2, 3><<<dim3(2048 / 128, KVROWS / 128), 256, GEMM_SMEM2>>>(
        kvh_, kvl_, Wkvh, k_raw, Vhp, KVROWS, 2048, HIDN);
    norm_rope3<0><<<(4 * NKV * KVL) / 8, 256>>>(k_raw, Khp, nullptr, kw, cosb, sinb,
                                                NKV, KVL, NKV * HD, 0, 1.0f);

    // ---- join, attention + O projection ----
    cudaStreamWaitEvent(0, evJoin, 0);

    attn4<<<4 * NH, 256, ATT_SMEM>>>(Qhp, Qlp, Khp, Vhp, ah, al);

    gemm3<0, 3, 2><<<dim3(HIDN / 128, (4 * QL) / 128), 256, GEMM_SMEM3>>>(
        ah, al, Woh, out, nullptr, 4 * QL, HIDN, HIDN);
}

// round 17
// speedup vs baseline: 1.7190x; 1.7190x over previous
#include <cuda_runtime.h>
#include <cuda_fp16.h>
#include <cstdint>

typedef __half f16;

#define CTXL 8192
#define QL   128
#define KVL  8320
#define HIDN 4096
#define NH   32
#define NKV  8
#define HD   128
#define KVROWS (4 * KVL)          // 33280

// ---------------- scratch ----------------
__device__ float g_q_raw[4 * QL * HIDN];
__device__ float g_k_raw[(size_t)KVROWS * NKV * HD];

__device__ f16 g_Wqh[(size_t)NH * HD * HIDN];
__device__ f16 g_Wkvh[(size_t)2 * NKV * HD * HIDN];
__device__ f16 g_Woh[(size_t)HIDN * NH * HD];
__device__ f16 g_hh[4 * QL * HIDN], g_hl[4 * QL * HIDN];
__device__ f16 g_kvh[(size_t)KVROWS * HIDN], g_kvl[(size_t)KVROWS * HIDN];
__device__ f16 g_Qh[4 * NH * QL * HD], g_Ql[4 * NH * QL * HD];
__device__ f16 g_Kh[(size_t)4 * NKV * KVL * HD];
__device__ f16 g_Vh[(size_t)KVROWS * NKV * HD];
__device__ f16 g_ah[4 * QL * HIDN];

// ================= helpers =================
__device__ __forceinline__ uint32_t smem_u32(const void* p) {
    uint32_t a;
    asm("{ .reg .u64 t; cvta.to.shared.u64 t, %1; cvt.u32.u64 %0, t; }" : "=r"(a) : "l"(p));
    return a;
}
__device__ __forceinline__ void ldsm_x4(uint32_t addr, uint32_t* r) {
    asm volatile("ldmatrix.sync.aligned.m8n8.x4.shared.b16 {%0,%1,%2,%3}, [%4];"
                 : "=r"(r[0]), "=r"(r[1]), "=r"(r[2]), "=r"(r[3]) : "r"(addr));
}
__device__ __forceinline__ void ldsm_x4_t(uint32_t addr, uint32_t* r) {
    asm volatile("ldmatrix.sync.aligned.m8n8.x4.trans.shared.b16 {%0,%1,%2,%3}, [%4];"
                 : "=r"(r[0]), "=r"(r[1]), "=r"(r[2]), "=r"(r[3]) : "r"(addr));
}
__device__ __forceinline__ void mma16816(float* c, const uint32_t* a, const uint32_t* b) {
    asm volatile(
        "mma.sync.aligned.m16n8k16.row.col.f32.f16.f16.f32 "
        "{%0,%1,%2,%3}, {%4,%5,%6,%7}, {%8,%9}, {%0,%1,%2,%3};"
        : "+f"(c[0]), "+f"(c[1]), "+f"(c[2]), "+f"(c[3])
        : "r"(a[0]), "r"(a[1]), "r"(a[2]), "r"(a[3]), "r"(b[0]), "r"(b[1]));
}
__device__ __forceinline__ void cpa16(uint32_t dst, const void* src) {
    asm volatile("cp.async.cg.shared.global [%0], [%1], 16;" :: "r"(dst), "l"(src));
}
__device__ __forceinline__ void cpa_commit() { asm volatile("cp.async.commit_group;"); }
template <int N>
__device__ __forceinline__ void cpa_wait() { asm volatile("cp.async.wait_group %0;" :: "n"(N)); }

__device__ __forceinline__ void split1h(float x, unsigned& h, unsigned& l) {
    f16 hb = __float2half_rn(x);
    float r = x - __half2float(hb);
    f16 lb = __float2half_rn(r);
    h = (unsigned)__half_as_ushort(hb);
    l = (unsigned)__half_as_ushort(lb);
}

// ---------------- conversion kernels ----------------
__global__ void split_pair(const float* __restrict__ in, f16* __restrict__ hi,
                           f16* __restrict__ lo, size_t n8)
{
    const size_t i = (size_t)blockIdx.x * 256 + threadIdx.x;
    if (i >= n8) return;
    const float* s = in + i * 8;
    unsigned h[8], l[8];
#pragma unroll
    for (int k = 0; k < 8; k++) split1h(s[k], h[k], l[k]);
    *(uint4*)(hi + i * 8) = make_uint4(h[0] | (h[1] << 16), h[2] | (h[3] << 16),
                                       h[4] | (h[5] << 16), h[6] | (h[7] << 16));
    *(uint4*)(lo + i * 8) = make_uint4(l[0] | (l[1] << 16), l[2] | (l[3] << 16),
                                       l[4] | (l[5] << 16), l[6] | (l[7] << 16));
}

__global__ void conv_hi(const float* __restrict__ in, f16* __restrict__ hi, size_t n8)
{
    const size_t i = (size_t)blockIdx.x * 256 + threadIdx.x;
    if (i >= n8) return;
    const float* s = in + i * 8;
    unsigned h[8];
#pragma unroll
    for (int k = 0; k < 8; k++)
        h[k] = (unsigned)__half_as_ushort(__float2half_rn(s[k]));
    *(uint4*)(hi + i * 8) = make_uint4(h[0] | (h[1] << 16), h[2] | (h[3] << 16),
                                       h[4] | (h[5] << 16), h[6] | (h[7] << 16));
}

__global__ void split_kv(const float* __restrict__ hidden, const float* __restrict__ target,
                         f16* __restrict__ hi, f16* __restrict__ lo)
{
    const int row = blockIdx.y;
    const int b = row / KVL;
    const int t = row - b * KVL;
    const float* src = (t < CTXL) ? target + ((size_t)b * CTXL + t) * HIDN
                                  : hidden + ((size_t)b * QL + (t - CTXL)) * HIDN;
    const int col = (blockIdx.x * 256 + threadIdx.x) * 8;
    const float* s = src + col;
    unsigned h[8], l[8];
#pragma unroll
    for (int k = 0; k < 8; k++) split1h(s[k], h[k], l[k]);
    *(uint4*)(hi + (size_t)row * HIDN + col) =
        make_uint4(h[0] | (h[1] << 16), h[2] | (h[3] << 16),
                   h[4] | (h[5] << 16), h[6] | (h[7] << 16));
    *(uint4*)(lo + (size_t)row * HIDN + col) =
        make_uint4(l[0] | (l[1] << 16), l[2] | (l[3] << 16),
                   l[4] | (l[5] << 16), l[6] | (l[7] << 16));
}

// ============ GEMM (R15): 128x128, 256 thr, KC=32, 3-stage, 2 CTAs/SM ============
// OUTMODE 0: fp32 C, 2-term A.
// OUTMODE 2: fused KV — K tiles (n0<1024): 2-term A, fp32 k_raw;
//            V tiles (n0>=1024): 1-term A, fp16 V plane.
// OUTMODE 3: fp32 C, 1-term A (Al unused) — O projection.
#define ROWB 80
#define TILEB (128 * ROWB)          // 10240
#define STAGEB (3 * TILEB)          // 30720 (Ah, Al, Bh)
#define GEMM_SMEM (3 * STAGEB)      // 92160 -> 2 CTAs/SM

template <int OUTMODE>
__global__ void __launch_bounds__(256, 2)
gemm3(const f16* __restrict__ Ah, const f16* __restrict__ Al,
      const f16* __restrict__ Bh,
      float* __restrict__ C, f16* __restrict__ Ch,
      int M, int N, int K)
{
    extern __shared__ char sm[];
    const uint32_t smb = smem_u32(sm);
    const int tid = threadIdx.x;
    const int l = tid & 31;
    const int w = tid >> 5;

    const int m0 = blockIdx.y * 128;
    const int n0 = blockIdx.x * 128;
    const bool useLo = (OUTMODE == 0) || (OUTMODE == 2 && n0 < 1024);

    const int lrow = tid >> 1;
    const int lseg = tid & 1;
    const f16* ah = Ah + (size_t)(m0 + lrow) * K + lseg * 16;
    const f16* al = (OUTMODE == 3) ? ah : Al + (size_t)(m0 + lrow) * K + lseg * 16;
    const f16* bh = Bh + (size_t)(n0 + lrow) * K + lseg * 16;
    const uint32_t soff = (uint32_t)lrow * ROWB + (uint32_t)lseg * 32;

    const int wm = (w & 3) * 32;
    const int wn = (w >> 2) * 64;
    const uint32_t a_off = (uint32_t)(wm + (l & 15)) * ROWB + (uint32_t)(l >> 4) * 16;
    const uint32_t b_off = (uint32_t)(wn + (l & 7) + ((l >> 4) & 1) * 8) * ROWB
                         + (uint32_t)((l >> 3) & 1) * 16;

    float acc[2][8][4];
#pragma unroll
    for (int i = 0; i < 2; i++)
#pragma unroll
        for (int j = 0; j < 8; j++)
#pragma unroll
            for (int k = 0; k < 4; k++) acc[i][j][k] = 0.f;

    const int nk = K / 32;

    auto issue = [&](int cc, int st) {
        const uint32_t s0 = smb + (uint32_t)st * STAGEB + soff;
        const int ko = cc * 32;
        cpa16(s0,             ah + ko);  cpa16(s0 + 16,             ah + ko + 8);
        if (useLo) {
            cpa16(s0 + TILEB,     al + ko);  cpa16(s0 + TILEB + 16,     al + ko + 8);
        }
        cpa16(s0 + 2 * TILEB, bh + ko);  cpa16(s0 + 2 * TILEB + 16, bh + ko + 8);
    };

    issue(0, 0); cpa_commit();
    issue(1, 1); cpa_commit();

    for (int c = 0; c < nk; ++c) {
        cpa_wait<1>();
        __syncthreads();
        if (c + 2 < nk) issue(c + 2, (c + 2) % 3);
        cpa_commit();

        const uint32_t base = smb + (uint32_t)(c % 3) * STAGEB;
#pragma unroll
        for (int ks = 0; ks < 2; ++ks) {
            uint32_t afh[2][4], afl[2][4];
            const uint32_t ka = base + a_off + ks * 32;
            ldsm_x4(ka, afh[0]);
            ldsm_x4(ka + 16 * ROWB, afh[1]);
            if (useLo) {
                ldsm_x4(ka + TILEB, afl[0]);
                ldsm_x4(ka + TILEB + 16 * ROWB, afl[1]);
            }

            const uint32_t kb = base + 2 * TILEB + b_off + ks * 32;
#pragma unroll
            for (int ng = 0; ng < 4; ++ng) {
                uint32_t bfh[4];
                ldsm_x4(kb + ng * 16 * ROWB, bfh);
#pragma unroll
                for (int mf = 0; mf < 2; ++mf) {
                    mma16816(acc[mf][ng * 2 + 0], afh[mf], bfh + 0);
                    mma16816(acc[mf][ng * 2 + 1], afh[mf], bfh + 2);
                }
                if (useLo) {
#pragma unroll
                    for (int mf = 0; mf < 2; ++mf) {
                        mma16816(acc[mf][ng * 2 + 0], afl[mf], bfh + 0);
                        mma16816(acc[mf][ng * 2 + 1], afl[mf], bfh + 2);
                    }
                }
            }
        }
    }

#pragma unroll
    for (int mf = 0; mf < 2; ++mf) {
        const int r0 = m0 + wm + mf * 16 + (l >> 2);
#pragma unroll
        for (int nf = 0; nf < 8; ++nf) {
            const int col = n0 + wn + nf * 8 + (l & 3) * 2;
            if (OUTMODE == 0 || OUTMODE == 3) {
                float* p = C + (size_t)r0 * N + col;
                *(float2*)p                   = make_float2(acc[mf][nf][0], acc[mf][nf][1]);
                *(float2*)(p + 8 * (size_t)N) = make_float2(acc[mf][nf][2], acc[mf][nf][3]);
            } else {
                if (n0 < 1024) {
                    float* p = C + (size_t)r0 * 1024 + col;
                    *(float2*)p              = make_float2(acc[mf][nf][0], acc[mf][nf][1]);
                    *(float2*)(p + 8 * 1024) = make_float2(acc[mf][nf][2], acc[mf][nf][3]);
                } else {
                    const int vcol = col - 1024;
                    unsigned h0 = (unsigned)__half_as_ushort(__float2half_rn(acc[mf][nf][0]));
                    unsigned h1 = (unsigned)__half_as_ushort(__float2half_rn(acc[mf][nf][1]));
                    unsigned h2 = (unsigned)__half_as_ushort(__float2half_rn(acc[mf][nf][2]));
                    unsigned h3 = (unsigned)__half_as_ushort(__float2half_rn(acc[mf][nf][3]));
                    *(uint32_t*)(Ch + (size_t)r0 * 1024 + vcol)       = h0 | (h1 << 16);
                    *(uint32_t*)(Ch + (size_t)(r0 + 8) * 1024 + vcol) = h2 | (h3 << 16);
                }
            }
        }
    }
}

// ---------------- norm+rope v3 (R12): one warp per head-row ----------------
template <int TWOPLANE>
__global__ void __launch_bounds__(256)
norm_rope3(const float* __restrict__ raw, f16* __restrict__ oh, f16* __restrict__ ol,
           const float* __restrict__ w,
           const float* __restrict__ cosb, const float* __restrict__ sinb,
           int heads, int seq, int rawld, int pos_off, float outscale)
{
    const int gid = blockIdx.x * 8 + (threadIdx.x >> 5);
    const int l = threadIdx.x & 31;
    const int t = gid % seq;
    const int h = (gid / seq) % heads;
    const int b = gid / (seq * heads);
    const int d = l * 4;

    const float4 x  = *(const float4*)(raw + ((size_t)(b * seq + t)) * rawld + h * HD + d);
    const float4 wv = *(const float4*)(w + d);
    float ss = x.x * x.x + x.y * x.y + x.z * x.z + x.w * x.w;
#pragma unroll
    for (int off = 16; off > 0; off >>= 1)
        ss += __shfl_xor_sync(0xffffffffu, ss, off);
    const float r = rsqrtf(ss * (1.0f / 128.0f) + 1e-6f);

    const float xn0 = x.x * r * wv.x;
    const float xn1 = x.y * r * wv.y;
    const float xn2 = x.z * r * wv.z;
    const float xn3 = x.w * r * wv.w;

    const float p0 = __shfl_xor_sync(0xffffffffu, xn0, 16);
    const float p1 = __shfl_xor_sync(0xffffffffu, xn1, 16);
    const float p2 = __shfl_xor_sync(0xffffffffu, xn2, 16);
    const float p3 = __shfl_xor_sync(0xffffffffu, xn3, 16);
    const float sgn = (l < 16) ? -1.f : 1.f;

    const size_t pidx = ((size_t)b * KVL + (size_t)(pos_off + t)) * HD + d;
    const float4 cv = *(const float4*)(cosb + pidx);
    const float4 sv = *(const float4*)(sinb + pidx);

    const float y0 = (xn0 * cv.x + sgn * p0 * sv.x) * outscale;
    const float y1 = (xn1 * cv.y + sgn * p1 * sv.y) * outscale;
    const float y2 = (xn2 * cv.z + sgn * p2 * sv.z) * outscale;
    const float y3 = (xn3 * cv.w + sgn * p3 * sv.w) * outscale;

    const size_t o = (((size_t)(b * heads + h)) * seq + t) * HD + d;
    if (TWOPLANE) {
        unsigned h0, l0, h1, l1, h2, l2, h3, l3;
        split1h(y0, h0, l0); split1h(y1, h1, l1);
        split1h(y2, h2, l2); split1h(y3, h3, l3);
        *(uint2*)(oh + o) = make_uint2(h0 | (h1 << 16), h2 | (h3 << 16));
        *(uint2*)(ol + o) = make_uint2(l0 | (l1 << 16), l2 | (l3 << 16));
    } else {
        const __half2 a = __floats2half2_rn(y0, y1);
        const __half2 bpk = __floats2half2_rn(y2, y3);
        *(uint2*)(oh + o) = make_uint2(*(const uint32_t*)&a, *(const uint32_t*)&bpk);
    }
}

// ---------------- flash attention (R12 + single-plane output) ----------------
#define QROWB 272
#define QTILE (128 * QROWB)
#define ATT_K0 (2 * QTILE)
#define ATT_V0 (4 * QTILE)
#define ATT_SMEM (6 * QTILE)
#define NCHUNK (KVL / 128)

__global__ void __launch_bounds__(256, 1)
attn4(const f16* __restrict__ Qh, const f16* __restrict__ Ql,
      const f16* __restrict__ Kh, const f16* __restrict__ Vh,
      f16* __restrict__ Oh)
{
    extern __shared__ char sm[];
    const uint32_t smb = smem_u32(sm);

    const int b   = blockIdx.x >> 5;
    const int h   = blockIdx.x & 31;
    const int kvh = h >> 2;
    const int tid = threadIdx.x;
    const int l = tid & 31;
    const int w = tid >> 5;

    const int row = tid >> 1;
    const int half = tid & 1;
    const uint32_t ld_off = (uint32_t)row * QROWB + (uint32_t)half * 128;

    {
        const f16* qh = Qh + ((size_t)(b * NH + h) * QL + row) * HD + half * 64;
        const f16* ql = Ql + ((size_t)(b * NH + h) * QL + row) * HD + half * 64;
#pragma unroll
        for (int i = 0; i < 8; i++) {
            cpa16(smb + ld_off + i * 16, qh + i * 8);
            cpa16(smb + QTILE + ld_off + i * 16, ql + i * 8);
        }
        cpa_commit();
    }

    const f16* kg = Kh + (size_t)(b * NKV + kvh) * KVL * HD;
    const f16* vg = Vh + (size_t)b * KVL * (NKV * HD) + kvh * HD;

    auto issue_chunk = [&](int cc) {
        const int st = cc & 1;
        const int t0 = cc * 128;
        const f16* s1 = kg + (size_t)(t0 + row) * HD + half * 64;
        const f16* s2 = vg + (size_t)(t0 + row) * (NKV * HD) + half * 64;
        const uint32_t kb = smb + ATT_K0 + (uint32_t)st * QTILE + ld_off;
        const uint32_t vb = smb + ATT_V0 + (uint32_t)st * QTILE + ld_off;
#pragma unroll
        for (int i = 0; i < 8; i++) {
            cpa16(kb + i * 16, s1 + i * 8);
            cpa16(vb + i * 16, s2 + i * 8);
        }
    };

    issue_chunk(0); cpa_commit();

    const int wq = w * 16;
    const uint32_t qa_off = (uint32_t)(wq + (l & 15)) * QROWB + (uint32_t)(l >> 4) * 16;
    const uint32_t kb_off = (uint32_t)((l & 7) + ((l >> 4) & 1) * 8) * QROWB
                          + (uint32_t)((l >> 3) & 1) * 16;
    const uint32_t vb_off = (uint32_t)(l & 15) * QROWB + (uint32_t)((l >> 4) & 1) * 16;

    float O[16][4];
    float mr[2], lr[2];
#pragma unroll
    for (int i = 0; i < 16; i++)
#pragma unroll
        for (int j = 0; j < 4; j++) O[i][j] = 0.f;
    mr[0] = mr[1] = -1e30f;
    lr[0] = lr[1] = 0.f;

    for (int c = 0; c < NCHUNK; ++c) {
        if (c + 1 < NCHUNK) issue_chunk(c + 1);
        cpa_commit();
        cpa_wait<1>();
        __syncthreads();

        const uint32_t sK = smb + ATT_K0 + (uint32_t)(c & 1) * QTILE;
        const uint32_t sV = smb + ATT_V0 + (uint32_t)(c & 1) * QTILE;

        float S[16][4];
#pragma unroll
        for (int i = 0; i < 16; i++)
#pragma unroll
            for (int j = 0; j < 4; j++) S[i][j] = 0.f;

#pragma unroll
        for (int ds = 0; ds < 8; ++ds) {
            uint32_t aqh[4], aql[4];
            ldsm_x4(smb + qa_off + ds * 32, aqh);
            ldsm_x4(smb + QTILE + qa_off + ds * 32, aql);
#pragma unroll
            for (int ng = 0; ng < 8; ++ng) {
                uint32_t bkh[4];
                ldsm_x4(sK + kb_off + ng * 16 * QROWB + ds * 32, bkh);
                mma16816(S[ng * 2 + 0], aqh, bkh + 0);
                mma16816(S[ng * 2 + 1], aqh, bkh + 2);
                mma16816(S[ng * 2 + 0], aql, bkh + 0);
                mma16816(S[ng * 2 + 1], aql, bkh + 2);
            }
        }

#pragma unroll
        for (int rr = 0; rr < 2; ++rr) {
            float mx = -1e30f;
#pragma unroll
            for (int t = 0; t < 16; t++)
                mx = fmaxf(mx, fmaxf(S[t][rr * 2], S[t][rr * 2 + 1]));
            mx = fmaxf(mx, __shfl_xor_sync(0xffffffffu, mx, 1));
            mx = fmaxf(mx, __shfl_xor_sync(0xffffffffu, mx, 2));
            const float mn = fmaxf(mr[rr], mx);
            const float corr = __expf(mr[rr] - mn);
            float rs = 0.f;
#pragma unroll
            for (int t = 0; t < 16; t++) {
                float p0 = __expf(S[t][rr * 2] - mn);
                float p1 = __expf(S[t][rr * 2 + 1] - mn);
                S[t][rr * 2] = p0;
                S[t][rr * 2 + 1] = p1;
                rs += p0 + p1;
            }
            rs += __shfl_xor_sync(0xffffffffu, rs, 1);
            rs += __shfl_xor_sync(0xffffffffu, rs, 2);
            lr[rr] = lr[rr] * corr + rs;
            mr[rr] = mn;
#pragma unroll
            for (int t = 0; t < 16; t++) {
                O[t][rr * 2] *= corr;
                O[t][rr * 2 + 1] *= corr;
            }
        }

#pragma unroll
        for (int s = 0; s < 8; ++s) {
            uint32_t ph[4];
#pragma unroll
            for (int q4 = 0; q4 < 4; ++q4) {
                const int t = 2 * s + (q4 >> 1);
                const __half2 pk = __floats2half2_rn(S[t][(q4 & 1) * 2],
                                                     S[t][(q4 & 1) * 2 + 1]);
                ph[q4] = *(const uint32_t*)&pk;
            }
#pragma unroll
            for (int ng = 0; ng < 8; ++ng) {
                uint32_t vbh[4];
                ldsm_x4_t(sV + vb_off + s * 16 * QROWB + ng * 32, vbh);
                mma16816(O[ng * 2 + 0], ph, vbh + 0);
                mma16816(O[ng * 2 + 1], ph, vbh + 2);
            }
        }
        __syncthreads();
    }

    const float inv0 = 1.0f / lr[0];
    const float inv1 = 1.0f / lr[1];
    const int q0 = wq + (l >> 2);
#pragma unroll
    for (int nf = 0; nf < 16; ++nf) {
        const int col = nf * 8 + (l & 3) * 2;
        const __half2 p0 = __floats2half2_rn(O[nf][0] * inv0, O[nf][1] * inv0);
        size_t o = ((size_t)(b * QL + q0)) * HIDN + h * HD + col;
        *(uint32_t*)(Oh + o) = *(const uint32_t*)&p0;
        const __half2 p1 = __floats2half2_rn(O[nf][2] * inv1, O[nf][3] * inv1);
        o = ((size_t)(b * QL + q0 + 8)) * HIDN + h * HD + col;
        *(uint32_t*)(Oh + o) = *(const uint32_t*)&p1;
    }
}

// ---------------- launcher: 3-stream capture-forked schedule ----------------
extern "C" void kernel_launch(void* const* d_in, const int* in_sizes, int n_in,
                              void* d_out, int out_size)
{
    const float* hidden = (const float*)d_in[0];
    const float* target = (const float*)d_in[1];
    const float* cosb   = (const float*)d_in[2];
    const float* sinb   = (const float*)d_in[3];
    const float* Wq     = (const float*)d_in[4];
    const float* Wk     = (const float*)d_in[5];
    const float* Wv     = (const float*)d_in[6];
    const float* Wo     = (const float*)d_in[7];
    const float* qw     = (const float*)d_in[8];
    const float* kw     = (const float*)d_in[9];
    float* out = (float*)d_out;

    float *q_raw, *k_raw;
    f16 *Wqh, *Wkvh, *Woh, *hh, *hl, *kvh_, *kvl_, *Qhp, *Qlp, *Khp, *Vhp, *ah;
    cudaGetSymbolAddress((void**)&q_raw, g_q_raw);
    cudaGetSymbolAddress((void**)&k_raw, g_k_raw);
    cudaGetSymbolAddress((void**)&Wqh, g_Wqh);
    cudaGetSymbolAddress((void**)&Wkvh, g_Wkvh);
    cudaGetSymbolAddress((void**)&Woh, g_Woh);
    cudaGetSymbolAddress((void**)&hh, g_hh);    cudaGetSymbolAddress((void**)&hl, g_hl);
    cudaGetSymbolAddress((void**)&kvh_, g_kvh); cudaGetSymbolAddress((void**)&kvl_, g_kvl);
    cudaGetSymbolAddress((void**)&Qhp, g_Qh);   cudaGetSymbolAddress((void**)&Qlp, g_Ql);
    cudaGetSymbolAddress((void**)&Khp, g_Kh);
    cudaGetSymbolAddress((void**)&Vhp, g_Vh);
    cudaGetSymbolAddress((void**)&ah, g_ah);

    cudaFuncSetAttribute(gemm3<0>, cudaFuncAttributeMaxDynamicSharedMemorySize, GEMM_SMEM);
    cudaFuncSetAttribute(gemm3<2>, cudaFuncAttributeMaxDynamicSharedMemorySize, GEMM_SMEM);
    cudaFuncSetAttribute(gemm3<3>, cudaFuncAttributeMaxDynamicSharedMemorySize, GEMM_SMEM);
    cudaFuncSetAttribute(attn4, cudaFuncAttributeMaxDynamicSharedMemorySize, ATT_SMEM);

    static cudaStream_t s2 = nullptr, s3 = nullptr;
    static cudaEvent_t evFork = nullptr, evJoin = nullptr, evW = nullptr;
    if (!s2) {
        cudaStreamCreateWithFlags(&s2, cudaStreamNonBlocking);
        cudaStreamCreateWithFlags(&s3, cudaStreamNonBlocking);
        cudaEventCreateWithFlags(&evFork, cudaEventDisableTiming);
        cudaEventCreateWithFlags(&evJoin, cudaEventDisableTiming);
        cudaEventCreateWithFlags(&evW, cudaEventDisableTiming);
    }

    const size_t WKV = (size_t)NKV * HD * HIDN;
    const float qscale = 0.08838834764831845f;

    // ---- fork ----
    cudaEventRecord(evFork, 0);
    cudaStreamWaitEvent(s2, evFork, 0);
    cudaStreamWaitEvent(s3, evFork, 0);

    // s3: KV weight converts
    conv_hi<<<(int)(WKV / 2048), 256, 0, s3>>>(Wk, Wkvh, WKV / 8);
    conv_hi<<<(int)(WKV / 2048), 256, 0, s3>>>(Wv, Wkvh + WKV, WKV / 8);
    cudaEventRecord(evW, s3);

    // s2: Q-chain + Wo convert
    conv_hi<<<(NH * HD * HIDN) / 2048, 256, 0, s2>>>(Wq, Wqh, (size_t)(NH * HD * HIDN) / 8);
    split_pair<<<(4 * QL * HIDN) / 2048, 256, 0, s2>>>(hidden, hh, hl,
                                                       (size_t)(4 * QL * HIDN) / 8);
    gemm3<0><<<dim3(HIDN / 128, (4 * QL) / 128), 256, GEMM_SMEM, s2>>>(
        hh, hl, Wqh, q_raw, nullptr, 4 * QL, HIDN, HIDN);
    norm_rope3<1><<<(4 * NH * QL) / 8, 256, 0, s2>>>(q_raw, Qhp, Qlp, qw, cosb, sinb,
                                                     NH, QL, HIDN, CTXL, qscale);
    conv_hi<<<(HIDN * NH * HD) / 2048, 256, 0, s2>>>(Wo, Woh, (size_t)(HIDN * NH * HD) / 8);
    cudaEventRecord(evJoin, s2);

    // main: KV-chain
    split_kv<<<dim3(HIDN / 2048, KVROWS), 256>>>(hidden, target, kvh_, kvl_);
    cudaStreamWaitEvent(0, evW, 0);
    gemm3<2><<<dim3(2048 / 128, KVROWS / 128), 256, GEMM_SMEM>>>(
        kvh_, kvl_, Wkvh, k_raw, Vhp, KVROWS, 2048, HIDN);
    norm_rope3<0><<<(4 * NKV * KVL) / 8, 256>>>(k_raw, Khp, nullptr, kw, cosb, sinb,
                                                NKV, KVL, NKV * HD, 0, 1.0f);

    // ---- join, attention + O projection (1-term) ----
    cudaStreamWaitEvent(0, evJoin, 0);

    attn4<<<4 * NH, 256, ATT_SMEM>>>(Qhp, Qlp, Khp, Vhp, ah);

    gemm3<3><<<dim3(HIDN / 128, (4 * QL) / 128), 256, GEMM_SMEM>>>(
        ah, nullptr, Woh, out, nullptr, 4 * QL, HIDN, HIDN);
}